// round 1
// baseline (speedup 1.0000x reference)
#include <cuda_runtime.h>
#include <cstdint>

// ---------------------------------------------------------------------------
// GeneralizedRCNNExtractModel: two big FC layers + cls/box heads + decode.
//   f6 = relu(x.reshape(R,D) @ W6 + b6)           R=2000, D=12544, H=1024
//   f7 = relu(f6 @ W7 + b7)
//   probs = softmax(f7 @ Wcls + bcls)             NC=81
//   reg   = (f7 @ Wbox + bbox_b).reshape(R,NC,4)
//   dec   = decode(reg, boxes); mask by probs>0.05 (classes 1..80)
//   out   = concat[scores_m(80), boxes_m(320), f6(1024)]  -> (R, 1424)
// ---------------------------------------------------------------------------

#define NUM_CLASSES 81
#define SCORE_THRESH 0.05f
// log(1000/16)
#define BBOX_XFORM_CLIP 4.135166556742356f

// scratch for f7 (R x H). No cudaMalloc allowed -> device global.
__device__ float g_f7[2000 * 1024];

// ---------------------------------------------------------------------------
// Tiled SGEMM with fused bias + ReLU.  C[M,N] = relu(A[M,K] @ B[K,N] + bias)
// A row-major with leading dim lda, B row-major (K x N) ldb, C ldc.
// BM=128, BN=128, BK=16, 256 threads, 8x8 per thread.
// Requires: K % 16 == 0, N % 128 == 0, lda%4==0, ldb%4==0, ldc%4==0,
//           col tiles fully in-bounds (N multiple of BN). Rows guarded vs M.
// ---------------------------------------------------------------------------
namespace cfg {
constexpr int BM = 128, BN = 128, BK = 16, TM = 8, TN = 8;
constexpr int THREADS = (BM / TM) * (BN / TN);  // 256
}

__global__ __launch_bounds__(cfg::THREADS)
void sgemm_bias_relu(int M, int N, int K,
                     const float* __restrict__ A, int lda,
                     const float* __restrict__ B, int ldb,
                     const float* __restrict__ bias,
                     float* __restrict__ C, int ldc) {
    using namespace cfg;
    __shared__ float As[BK][BM];   // transposed: As[k][m]
    __shared__ float Bs[BK][BN];

    const int tid = threadIdx.x;
    const int bm = blockIdx.y * BM;
    const int bn = blockIdx.x * BN;

    // A tile loader: 128x16 floats = 512 float4; 2 per thread.
    const int aRow = tid / (BK / 4);          // 0..63
    const int aCol = (tid % (BK / 4)) * 4;    // 0,4,8,12
    // B tile loader: 16x128 floats = 512 float4; 2 per thread.
    const int bRow = tid / (BN / 4);          // 0..7
    const int bCol = (tid % (BN / 4)) * 4;

    const int trow = (tid / (BN / TN)) * TM;  // 0..120 step 8
    const int tcol = (tid % (BN / TN)) * TN;

    float acc[TM][TN];
#pragma unroll
    for (int i = 0; i < TM; ++i)
#pragma unroll
        for (int j = 0; j < TN; ++j) acc[i][j] = 0.f;

    for (int k0 = 0; k0 < K; k0 += BK) {
        // ---- load A tile (transpose into As) ----
#pragma unroll
        for (int r = 0; r < BM; r += 64) {
            const int grow = bm + aRow + r;
            float4 v = make_float4(0.f, 0.f, 0.f, 0.f);
            if (grow < M)
                v = *reinterpret_cast<const float4*>(
                    &A[(size_t)grow * lda + k0 + aCol]);
            As[aCol + 0][aRow + r] = v.x;
            As[aCol + 1][aRow + r] = v.y;
            As[aCol + 2][aRow + r] = v.z;
            As[aCol + 3][aRow + r] = v.w;
        }
        // ---- load B tile ----
#pragma unroll
        for (int r = 0; r < BK; r += 8) {
            const float4 v = *reinterpret_cast<const float4*>(
                &B[(size_t)(k0 + bRow + r) * ldb + bn + bCol]);
            *reinterpret_cast<float4*>(&Bs[bRow + r][bCol]) = v;
        }
        __syncthreads();

#pragma unroll
        for (int k = 0; k < BK; ++k) {
            float ra[TM], rb[TN];
#pragma unroll
            for (int i = 0; i < TM; ++i) ra[i] = As[k][trow + i];
#pragma unroll
            for (int j = 0; j < TN; ++j) rb[j] = Bs[k][tcol + j];
#pragma unroll
            for (int i = 0; i < TM; ++i)
#pragma unroll
                for (int j = 0; j < TN; ++j)
                    acc[i][j] = fmaf(ra[i], rb[j], acc[i][j]);
        }
        __syncthreads();
    }

    // ---- epilogue: bias + relu, vectorized stores ----
#pragma unroll
    for (int i = 0; i < TM; ++i) {
        const int grow = bm + trow + i;
        if (grow >= M) continue;
#pragma unroll
        for (int j = 0; j < TN; j += 4) {
            const int gcol = bn + tcol + j;
            float4 v;
            v.x = fmaxf(acc[i][j + 0] + bias[gcol + 0], 0.f);
            v.y = fmaxf(acc[i][j + 1] + bias[gcol + 1], 0.f);
            v.z = fmaxf(acc[i][j + 2] + bias[gcol + 2], 0.f);
            v.w = fmaxf(acc[i][j + 3] + bias[gcol + 3], 0.f);
            *reinterpret_cast<float4*>(&C[(size_t)grow * ldc + gcol]) = v;
        }
    }
}

// ---------------------------------------------------------------------------
// Head kernel: one block per ROI row.
//   logits = f7row @ Wcls + bcls   (81)
//   reg    = f7row @ Wbox + bbox_b (324)
//   softmax, decode, mask, write out cols [0, 400)
// ---------------------------------------------------------------------------
__global__ __launch_bounds__(256)
void head_kernel(int H,
                 const float* __restrict__ f7,
                 const float* __restrict__ Wcls,
                 const float* __restrict__ bcls,
                 const float* __restrict__ Wbox,
                 const float* __restrict__ bbox_b,
                 const float* __restrict__ boxes,
                 float* __restrict__ out, int ldo) {
    const int r = blockIdx.x;
    const int t = threadIdx.x;

    __shared__ float sf[1024];
    __shared__ float slog[NUM_CLASSES];
    __shared__ float sreg[NUM_CLASSES * 4];
    __shared__ float smax, ssum;

    for (int i = t; i < H; i += blockDim.x) sf[i] = f7[(size_t)r * H + i];
    __syncthreads();

    // class logits (81 cols): thread t -> column t. Coalesced W reads.
    for (int c = t; c < NUM_CLASSES; c += blockDim.x) {
        float acc = bcls[c];
#pragma unroll 4
        for (int h = 0; h < H; ++h)
            acc = fmaf(sf[h], Wcls[(size_t)h * NUM_CLASSES + c], acc);
        slog[c] = acc;
    }
    // box regression (324 cols)
    for (int c = t; c < NUM_CLASSES * 4; c += blockDim.x) {
        float acc = bbox_b[c];
#pragma unroll 4
        for (int h = 0; h < H; ++h)
            acc = fmaf(sf[h], Wbox[(size_t)h * (NUM_CLASSES * 4) + c], acc);
        sreg[c] = acc;
    }
    __syncthreads();

    if (t == 0) {
        float m = -1e30f;
        for (int i = 0; i < NUM_CLASSES; ++i) m = fmaxf(m, slog[i]);
        float s = 0.f;
        for (int i = 0; i < NUM_CLASSES; ++i) s += expf(slog[i] - m);
        smax = m;
        ssum = s;
    }
    __syncthreads();

    // classes 1..80 -> thread t in [0,80)
    if (t < NUM_CLASSES - 1) {
        const int j = t + 1;
        const float p = expf(slog[j] - smax) / ssum;
        const bool keep = p > SCORE_THRESH;

        const float bx0 = boxes[r * 4 + 0];
        const float by0 = boxes[r * 4 + 1];
        const float bx1 = boxes[r * 4 + 2];
        const float by1 = boxes[r * 4 + 3];
        const float w = bx1 - bx0 + 1.0f;
        const float hh = by1 - by0 + 1.0f;
        const float cx = bx0 + 0.5f * w;
        const float cy = by0 + 0.5f * hh;

        const float dx = sreg[j * 4 + 0] * 0.1f;
        const float dy = sreg[j * 4 + 1] * 0.1f;
        const float dw = fminf(sreg[j * 4 + 2] * 0.2f, BBOX_XFORM_CLIP);
        const float dh = fminf(sreg[j * 4 + 3] * 0.2f, BBOX_XFORM_CLIP);

        const float pcx = dx * w + cx;
        const float pcy = dy * hh + cy;
        const float pw = expf(dw) * w;
        const float ph = expf(dh) * hh;

        float d0 = pcx - 0.5f * pw;
        float d1 = pcy - 0.5f * ph;
        float d2 = pcx + 0.5f * pw - 1.0f;
        float d3 = pcy + 0.5f * ph - 1.0f;

        float* orow = out + (size_t)r * ldo;
        orow[t] = keep ? p : 0.f;
        const int bo = (NUM_CLASSES - 1) + t * 4;
        orow[bo + 0] = keep ? d0 : 0.f;
        orow[bo + 1] = keep ? d1 : 0.f;
        orow[bo + 2] = keep ? d2 : 0.f;
        orow[bo + 3] = keep ? d3 : 0.f;
    }
}

// ---------------------------------------------------------------------------
// Launch
// inputs: 0:x 1:boxes 2:W6 3:b6 4:W7 5:b7 6:Wcls 7:bcls 8:Wbox 9:bbox_b
// ---------------------------------------------------------------------------
extern "C" void kernel_launch(void* const* d_in, const int* in_sizes, int n_in,
                              void* d_out, int out_size) {
    const float* x      = (const float*)d_in[0];
    const float* boxes  = (const float*)d_in[1];
    const float* W6     = (const float*)d_in[2];
    const float* b6     = (const float*)d_in[3];
    const float* W7     = (const float*)d_in[4];
    const float* b7     = (const float*)d_in[5];
    const float* Wcls   = (const float*)d_in[6];
    const float* bcls   = (const float*)d_in[7];
    const float* Wbox   = (const float*)d_in[8];
    const float* bbox_b = (const float*)d_in[9];
    float* out = (float*)d_out;

    const int M  = in_sizes[1] / 4;        // 2000
    const int K1 = in_sizes[0] / M;        // 12544
    const int H  = in_sizes[3];            // 1024
    const int NC = in_sizes[7];            // 81
    const int OUTW = (NC - 1) + (NC - 1) * 4 + H;  // 1424
    (void)n_in; (void)out_size;

    float* f7;
    cudaGetSymbolAddress((void**)&f7, g_f7);

    using namespace cfg;
    // GEMM1: f6 = relu(x @ W6 + b6) written into out cols [400, 1424)
    {
        dim3 grid(H / BN, (M + BM - 1) / BM);
        sgemm_bias_relu<<<grid, THREADS>>>(M, H, K1, x, K1, W6, H, b6,
                                           out + (NC - 1) * 5, OUTW);
    }
    // GEMM2: f7 = relu(f6 @ W7 + b7), f6 read from out (lda = OUTW)
    {
        dim3 grid(H / BN, (M + BM - 1) / BM);
        sgemm_bias_relu<<<grid, THREADS>>>(M, H, H, out + (NC - 1) * 5, OUTW,
                                           W7, H, b7, f7, H);
    }
    // Head: one block per row
    head_kernel<<<M, 256>>>(H, f7, Wcls, bcls, Wbox, bbox_b, boxes, out, OUTW);
}

// round 3
// speedup vs baseline: 2.6544x; 2.6544x over previous
#include <cuda_runtime.h>
#include <cuda_bf16.h>
#include <cstdint>

// ---------------------------------------------------------------------------
// GeneralizedRCNNExtractModel via HMMA (mma.sync bf16) split-fp32 GEMMs.
// tcgen05 is unavailable (harness compiles for compute_103, no 'a' features).
//   f6     = relu(x @ W6 + b6)            2000x12544 @ 12544x1024
//   f7     = relu(f6 @ W7 + b7)           2000x1024  @ 1024x1024
//   logits = f7 @ [Wcls|Wbox] + [bcls|bbox_b]   2000x1024 @ 1024x405 (pad 512)
//   postprocess: softmax(81), decode, threshold-mask, scatter into out.
// fp32 emulated as 3 accumulating bf16 passes: Ah@Bh + Ah@Bl + Al@Bh.
// ---------------------------------------------------------------------------

#define NUM_CLASSES 81
#define SCORE_THRESH 0.05f
#define BBOX_XFORM_CLIP 4.135166556742356f

#define RMAX 2000
#define KDIM 12544
#define HDIM 1024
#define NHEAD 512   // 405 used, padded

// --------------------------- device scratch -------------------------------
__device__ __nv_bfloat16 g_xh[RMAX * KDIM];
__device__ __nv_bfloat16 g_xl[RMAX * KDIM];
__device__ __nv_bfloat16 g_w6h[HDIM * KDIM];    // [N][K]
__device__ __nv_bfloat16 g_w6l[HDIM * KDIM];
__device__ __nv_bfloat16 g_w7h[HDIM * HDIM];
__device__ __nv_bfloat16 g_w7l[HDIM * HDIM];
__device__ __nv_bfloat16 g_whh[NHEAD * HDIM];   // rows 405..511 stay zero (.bss)
__device__ __nv_bfloat16 g_whl[NHEAD * HDIM];
__device__ float         g_bhead[NHEAD];
__device__ __nv_bfloat16 g_f6h[RMAX * HDIM];
__device__ __nv_bfloat16 g_f6l[RMAX * HDIM];
__device__ __nv_bfloat16 g_f7h[RMAX * HDIM];
__device__ __nv_bfloat16 g_f7l[RMAX * HDIM];
__device__ float         g_logits[RMAX * NHEAD];

// --------------------------- PTX helpers ----------------------------------
__device__ __forceinline__ uint32_t smem_to_u32(const void* p) {
    uint32_t a;
    asm("{ .reg .u64 t; cvta.to.shared.u64 t, %1; cvt.u32.u64 %0, t; }"
        : "=r"(a) : "l"(p));
    return a;
}
__device__ __forceinline__ void cp_async16(uint32_t dst, const void* src, bool pred) {
    int sz = pred ? 16 : 0;
    asm volatile("cp.async.cg.shared.global [%0], [%1], 16, %2;"
                 :: "r"(dst), "l"(src), "r"(sz) : "memory");
}
#define CP_COMMIT() asm volatile("cp.async.commit_group;" ::: "memory")
#define CP_WAIT(N)  asm volatile("cp.async.wait_group %0;" :: "n"(N) : "memory")

__device__ __forceinline__ void ldsm_x4(uint32_t& r0, uint32_t& r1,
                                        uint32_t& r2, uint32_t& r3, uint32_t addr) {
    asm volatile("ldmatrix.sync.aligned.m8n8.x4.shared.b16 {%0,%1,%2,%3}, [%4];"
                 : "=r"(r0), "=r"(r1), "=r"(r2), "=r"(r3) : "r"(addr));
}
__device__ __forceinline__ void mma16816(float* c, const uint32_t* a,
                                         uint32_t b0, uint32_t b1) {
    asm volatile(
        "mma.sync.aligned.m16n8k16.row.col.f32.bf16.bf16.f32 "
        "{%0,%1,%2,%3}, {%4,%5,%6,%7}, {%8,%9}, {%0,%1,%2,%3};"
        : "+f"(c[0]), "+f"(c[1]), "+f"(c[2]), "+f"(c[3])
        : "r"(a[0]), "r"(a[1]), "r"(a[2]), "r"(a[3]), "r"(b0), "r"(b1));
}

// swizzled smem offset for (row, 16B-chunk) with 64B logical rows:
// phys = row*64 + ((chunk ^ ((row>>1)&3)) << 4)   -> conflict-free ldmatrix/STS.
__device__ __forceinline__ uint32_t swoff(int row, int chunk) {
    return (uint32_t)(row * 64 + ((chunk ^ ((row >> 1) & 3)) << 4));
}

// --------------------------- conversion kernels ---------------------------
__global__ void split_f32_kernel(const float* __restrict__ X, size_t n4,
                                 __nv_bfloat16* __restrict__ Xh,
                                 __nv_bfloat16* __restrict__ Xl) {
    size_t i = (size_t)blockIdx.x * blockDim.x + threadIdx.x;
    size_t stride = (size_t)gridDim.x * blockDim.x;
    const float4* X4 = reinterpret_cast<const float4*>(X);
    __nv_bfloat162* H2 = reinterpret_cast<__nv_bfloat162*>(Xh);
    __nv_bfloat162* L2 = reinterpret_cast<__nv_bfloat162*>(Xl);
    for (; i < n4; i += stride) {
        float4 v = X4[i];
        __nv_bfloat16 hx = __float2bfloat16(v.x), hy = __float2bfloat16(v.y);
        __nv_bfloat16 hz = __float2bfloat16(v.z), hw = __float2bfloat16(v.w);
        __nv_bfloat16 lx = __float2bfloat16(v.x - __bfloat162float(hx));
        __nv_bfloat16 ly = __float2bfloat16(v.y - __bfloat162float(hy));
        __nv_bfloat16 lz = __float2bfloat16(v.z - __bfloat162float(hz));
        __nv_bfloat16 lw = __float2bfloat16(v.w - __bfloat162float(hw));
        H2[i * 2 + 0] = __nv_bfloat162(hx, hy);
        H2[i * 2 + 1] = __nv_bfloat162(hz, hw);
        L2[i * 2 + 0] = __nv_bfloat162(lx, ly);
        L2[i * 2 + 1] = __nv_bfloat162(lz, lw);
    }
}

// W[K][Nsrc] f32 -> Th/Tl[rowoff + n][K] bf16 (transpose + split), n guarded.
__global__ void transpose_split_kernel(const float* __restrict__ W, int K, int Nsrc,
                                       int ldT, int rowoff,
                                       __nv_bfloat16* __restrict__ Th,
                                       __nv_bfloat16* __restrict__ Tl) {
    __shared__ float t[32][33];
    const int n0 = blockIdx.x * 32;
    const int k0 = blockIdx.y * 32;
    const int tx = threadIdx.x, ty = threadIdx.y;  // 32 x 8
#pragma unroll
    for (int i = 0; i < 32; i += 8) {
        float v = 0.f;
        if (n0 + tx < Nsrc)
            v = W[(size_t)(k0 + ty + i) * Nsrc + n0 + tx];
        t[ty + i][tx] = v;
    }
    __syncthreads();
#pragma unroll
    for (int i = 0; i < 32; i += 8) {
        const int n = n0 + ty + i;
        if (n >= Nsrc) continue;
        float v = t[tx][ty + i];
        __nv_bfloat16 h = __float2bfloat16(v);
        __nv_bfloat16 l = __float2bfloat16(v - __bfloat162float(h));
        const size_t o = (size_t)(rowoff + n) * ldT + k0 + tx;
        Th[o] = h;
        Tl[o] = l;
    }
}

__global__ void bias_head_kernel(const float* __restrict__ bcls,
                                 const float* __restrict__ bbox_b,
                                 float* __restrict__ bh) {
    int t = threadIdx.x;  // 512
    float v = 0.f;
    if (t < NUM_CLASSES) v = bcls[t];
    else if (t < NUM_CLASSES + NUM_CLASSES * 4) v = bbox_b[t - NUM_CLASSES];
    bh[t] = v;
}

// --------------------------- HMMA split GEMM ------------------------------
// C[M,N] (opt) = maybe_relu(A @ B^T + bias); A split [M][K] bf16, B split [N][K].
// 3 accumulating passes in registers. Block 128x128x32, 8 warps (32x64 tiles),
// 3-stage cp.async pipeline. Requires K%32==0, N%128==0. Rows guarded vs M.
__global__ __launch_bounds__(256, 1)
void hmma_gemm_split(int M, int N, int K,
                     const __nv_bfloat16* __restrict__ Ah,
                     const __nv_bfloat16* __restrict__ Al,
                     const __nv_bfloat16* __restrict__ Bh,
                     const __nv_bfloat16* __restrict__ Bl,
                     const float* __restrict__ bias, int do_relu,
                     float* __restrict__ C, int ldc,
                     __nv_bfloat16* __restrict__ Oh,
                     __nv_bfloat16* __restrict__ Ol, int ldo) {
    __shared__ char smem[49152];  // 3 stages x (A 8KB + B 8KB)
    const uint32_t sbase = smem_to_u32(smem);
    const int tid = threadIdx.x, lane = tid & 31, wid = tid >> 5;
    const int bm = blockIdx.y * 128, bn = blockIdx.x * 128;
    const int wm = (wid & 3) * 32, wn = (wid >> 2) * 64;

    // ---- cp.async per-thread addressing (step-invariant parts) ----
    uint32_t offA[2], offB[2];
    size_t gofA[2], gofB[2];
    bool predA[2];
#pragma unroll
    for (int i = 0; i < 2; ++i) {
        const int idx = tid + i * 256;           // 0..511
        const int row = idx >> 2, ch = idx & 3;  // 128 rows x 4 chunks(16B)
        offA[i] = swoff(row, ch);
        offB[i] = swoff(row, ch);
        const int ra = (bm + row < M) ? (bm + row) : (M - 1);
        predA[i] = (bm + row < M);
        gofA[i] = (size_t)ra * K + ch * 8;
        gofB[i] = (size_t)(bn + row) * K + ch * 8;
    }

    // ---- ldmatrix per-thread fragment offsets (within a stage) ----
    // A: matrices [m0-7 k0][m8-15 k0][m0-7 k8][m8-15 k8]
    uint32_t aFrag[2][2];
#pragma unroll
    for (int mt = 0; mt < 2; ++mt) {
        const int row = wm + mt * 16 + (lane & 15);
#pragma unroll
        for (int kc = 0; kc < 2; ++kc) {
            const int ch = (lane >> 4) + kc * 2;
            aFrag[mt][kc] = swoff(row, ch);
        }
    }
    // B: matrices [n0-7 k0][n0-7 k8][n8-15 k0][n8-15 k8]
    uint32_t bFrag[4][2];
#pragma unroll
    for (int nt = 0; nt < 4; ++nt) {
        const int row = wn + nt * 16 + ((lane & 7) | ((lane >> 4) << 3));
#pragma unroll
        for (int kc = 0; kc < 2; ++kc) {
            const int ch = ((lane >> 3) & 1) + kc * 2;
            bFrag[nt][kc] = swoff(row, ch);
        }
    }

    float acc[2][8][4];
#pragma unroll
    for (int mt = 0; mt < 2; ++mt)
#pragma unroll
        for (int nf = 0; nf < 8; ++nf)
#pragma unroll
            for (int k = 0; k < 4; ++k) acc[mt][nf][k] = 0.f;

    const int spp = K / 32;
    const int S = 3 * spp;

    auto issue = [&](int step) {
        const int pass = step / spp;
        const int k0 = (step - pass * spp) * 32;
        const __nv_bfloat16* Ap = (pass == 2) ? Al : Ah;
        const __nv_bfloat16* Bp = (pass == 1) ? Bl : Bh;
        const uint32_t st = (uint32_t)(step % 3) * 16384u;
#pragma unroll
        for (int i = 0; i < 2; ++i)
            cp_async16(sbase + st + offA[i], Ap + gofA[i] + k0, predA[i]);
#pragma unroll
        for (int i = 0; i < 2; ++i)
            cp_async16(sbase + st + 8192 + offB[i], Bp + gofB[i] + k0, true);
        CP_COMMIT();
    };

    issue(0);
    issue(1);

#pragma unroll 1
    for (int s = 0; s < S; ++s) {
        if (s + 1 < S) { CP_WAIT(1); } else { CP_WAIT(0); }
        __syncthreads();
        if (s + 2 < S) issue(s + 2);

        const uint32_t baseA = sbase + (uint32_t)(s % 3) * 16384u;
        const uint32_t baseB = baseA + 8192u;
#pragma unroll
        for (int kc = 0; kc < 2; ++kc) {
            uint32_t a[2][4];
            ldsm_x4(a[0][0], a[0][1], a[0][2], a[0][3], baseA + aFrag[0][kc]);
            ldsm_x4(a[1][0], a[1][1], a[1][2], a[1][3], baseA + aFrag[1][kc]);
#pragma unroll
            for (int nt = 0; nt < 4; ++nt) {
                uint32_t b0, b1, b2, b3;
                ldsm_x4(b0, b1, b2, b3, baseB + bFrag[nt][kc]);
                mma16816(acc[0][nt * 2 + 0], a[0], b0, b1);
                mma16816(acc[0][nt * 2 + 1], a[0], b2, b3);
                mma16816(acc[1][nt * 2 + 0], a[1], b0, b1);
                mma16816(acc[1][nt * 2 + 1], a[1], b2, b3);
            }
        }
    }

    // ---- epilogue: bias (+relu), write C f32 and/or split bf16 ----
#pragma unroll
    for (int mt = 0; mt < 2; ++mt) {
#pragma unroll
        for (int nf = 0; nf < 8; ++nf) {
            const int col = bn + wn + nf * 8 + (lane & 3) * 2;
            const float b0 = bias[col], b1 = bias[col + 1];
#pragma unroll
            for (int half = 0; half < 2; ++half) {
                const int row = bm + wm + mt * 16 + (lane >> 2) + half * 8;
                if (row >= M) continue;
                float v0 = acc[mt][nf][half * 2 + 0] + b0;
                float v1 = acc[mt][nf][half * 2 + 1] + b1;
                if (do_relu) { v0 = fmaxf(v0, 0.f); v1 = fmaxf(v1, 0.f); }
                if (C)
                    *reinterpret_cast<float2*>(&C[(size_t)row * ldc + col]) =
                        make_float2(v0, v1);
                if (Oh) {
                    __nv_bfloat16 h0 = __float2bfloat16(v0);
                    __nv_bfloat16 h1 = __float2bfloat16(v1);
                    __nv_bfloat16 l0 = __float2bfloat16(v0 - __bfloat162float(h0));
                    __nv_bfloat16 l1 = __float2bfloat16(v1 - __bfloat162float(h1));
                    *reinterpret_cast<__nv_bfloat162*>(&Oh[(size_t)row * ldo + col]) =
                        __nv_bfloat162(h0, h1);
                    *reinterpret_cast<__nv_bfloat162*>(&Ol[(size_t)row * ldo + col]) =
                        __nv_bfloat162(l0, l1);
                }
            }
        }
    }
}

// --------------------------- postprocess ----------------------------------
// one block (128 thr) per ROI: softmax over 81 logits, decode, mask, write
// out cols [0, 400). logits row layout: [0..80]=cls, [81..404]=box reg.
__global__ __launch_bounds__(128)
void postprocess_kernel(const float* __restrict__ logits, int ldl,
                        const float* __restrict__ boxes,
                        float* __restrict__ out, int ldo) {
    const int r = blockIdx.x;
    const int t = threadIdx.x;
    __shared__ float sl[NUM_CLASSES * 5];  // 405
    __shared__ float smax, ssum;

    for (int i = t; i < NUM_CLASSES * 5; i += 128)
        sl[i] = logits[(size_t)r * ldl + i];
    __syncthreads();

    if (t == 0) {
        float m = -1e30f;
        for (int i = 0; i < NUM_CLASSES; ++i) m = fmaxf(m, sl[i]);
        float s = 0.f;
        for (int i = 0; i < NUM_CLASSES; ++i) s += expf(sl[i] - m);
        smax = m;
        ssum = s;
    }
    __syncthreads();

    if (t < NUM_CLASSES - 1) {
        const int j = t + 1;
        const float p = expf(sl[j] - smax) / ssum;
        const bool keep = p > SCORE_THRESH;

        const float bx0 = boxes[r * 4 + 0];
        const float by0 = boxes[r * 4 + 1];
        const float bx1 = boxes[r * 4 + 2];
        const float by1 = boxes[r * 4 + 3];
        const float w = bx1 - bx0 + 1.0f;
        const float hh = by1 - by0 + 1.0f;
        const float cx = bx0 + 0.5f * w;
        const float cy = by0 + 0.5f * hh;

        const float* reg = &sl[NUM_CLASSES + j * 4];
        const float dx = reg[0] * 0.1f;
        const float dy = reg[1] * 0.1f;
        const float dw = fminf(reg[2] * 0.2f, BBOX_XFORM_CLIP);
        const float dh = fminf(reg[3] * 0.2f, BBOX_XFORM_CLIP);

        const float pcx = dx * w + cx;
        const float pcy = dy * hh + cy;
        const float pw = expf(dw) * w;
        const float ph = expf(dh) * hh;

        float* orow = out + (size_t)r * ldo;
        orow[t] = keep ? p : 0.f;
        const int bo = (NUM_CLASSES - 1) + t * 4;
        orow[bo + 0] = keep ? (pcx - 0.5f * pw) : 0.f;
        orow[bo + 1] = keep ? (pcy - 0.5f * ph) : 0.f;
        orow[bo + 2] = keep ? (pcx + 0.5f * pw - 1.0f) : 0.f;
        orow[bo + 3] = keep ? (pcy + 0.5f * ph - 1.0f) : 0.f;
    }
}

// --------------------------- launch ---------------------------------------
extern "C" void kernel_launch(void* const* d_in, const int* in_sizes, int n_in,
                              void* d_out, int out_size) {
    const float* x      = (const float*)d_in[0];
    const float* boxes  = (const float*)d_in[1];
    const float* W6     = (const float*)d_in[2];
    const float* b6     = (const float*)d_in[3];
    const float* W7     = (const float*)d_in[4];
    const float* b7     = (const float*)d_in[5];
    const float* Wcls   = (const float*)d_in[6];
    const float* bcls   = (const float*)d_in[7];
    const float* Wbox   = (const float*)d_in[8];
    const float* bbox_b = (const float*)d_in[9];
    float* out = (float*)d_out;
    (void)n_in; (void)out_size;

    const int M  = in_sizes[1] / 4;       // 2000
    const int K1 = in_sizes[0] / M;       // 12544
    const int H  = in_sizes[3];           // 1024
    const int NC = in_sizes[7];           // 81
    const int OUTW = (NC - 1) * 5 + H;    // 1424

    __nv_bfloat16 *xh, *xl, *w6h, *w6l, *w7h, *w7l, *whh, *whl;
    __nv_bfloat16 *f6h, *f6l, *f7h, *f7l;
    float *bhead, *logits;
    cudaGetSymbolAddress((void**)&xh, g_xh);
    cudaGetSymbolAddress((void**)&xl, g_xl);
    cudaGetSymbolAddress((void**)&w6h, g_w6h);
    cudaGetSymbolAddress((void**)&w6l, g_w6l);
    cudaGetSymbolAddress((void**)&w7h, g_w7h);
    cudaGetSymbolAddress((void**)&w7l, g_w7l);
    cudaGetSymbolAddress((void**)&whh, g_whh);
    cudaGetSymbolAddress((void**)&whl, g_whl);
    cudaGetSymbolAddress((void**)&bhead, g_bhead);
    cudaGetSymbolAddress((void**)&f6h, g_f6h);
    cudaGetSymbolAddress((void**)&f6l, g_f6l);
    cudaGetSymbolAddress((void**)&f7h, g_f7h);
    cudaGetSymbolAddress((void**)&f7l, g_f7l);
    cudaGetSymbolAddress((void**)&logits, g_logits);

    // 1) split x
    split_f32_kernel<<<4096, 256>>>(x, ((size_t)M * K1) / 4, xh, xl);
    // 2) transpose+split weights
    transpose_split_kernel<<<dim3(H / 32, K1 / 32), dim3(32, 8)>>>(
        W6, K1, H, K1, 0, w6h, w6l);
    transpose_split_kernel<<<dim3(H / 32, H / 32), dim3(32, 8)>>>(
        W7, H, H, H, 0, w7h, w7l);
    transpose_split_kernel<<<dim3((NC + 31) / 32, H / 32), dim3(32, 8)>>>(
        Wcls, H, NC, H, 0, whh, whl);
    transpose_split_kernel<<<dim3((NC * 4 + 31) / 32, H / 32), dim3(32, 8)>>>(
        Wbox, H, NC * 4, H, NC, whh, whl);
    bias_head_kernel<<<1, NHEAD>>>(bcls, bbox_b, bhead);

    // 3) GEMM1: f6 -> out cols [400,1424) (f32) + split copy
    hmma_gemm_split<<<dim3(H / 128, (M + 127) / 128), 256>>>(
        M, H, K1, xh, xl, w6h, w6l, b6, 1,
        out + (NC - 1) * 5, OUTW, f6h, f6l, H);
    // 4) GEMM2: f7 split only
    hmma_gemm_split<<<dim3(H / 128, (M + 127) / 128), 256>>>(
        M, H, H, f6h, f6l, w7h, w7l, b7, 1,
        nullptr, 0, f7h, f7l, H);
    // 5) head GEMM: logits (no relu)
    hmma_gemm_split<<<dim3(NHEAD / 128, (M + 127) / 128), 256>>>(
        M, NHEAD, H, f7h, f7l, whh, whl, bhead, 0,
        logits, NHEAD, nullptr, nullptr, 0);
    // 6) postprocess
    postprocess_kernel<<<M, 128>>>(logits, NHEAD, boxes, out, OUTW);
}

// round 4
// speedup vs baseline: 4.0751x; 1.5352x over previous
#include <cuda_runtime.h>
#include <cuda_bf16.h>
#include <cstdint>

// ---------------------------------------------------------------------------
// GeneralizedRCNNExtractModel via HMMA (mma.sync bf16) split-fp32 GEMMs.
//   f6     = relu(x @ W6 + b6)            2000x12544 @ 12544x1024
//   f7     = relu(f6 @ W7 + b7)           2000x1024  @ 1024x1024
//   logits = f7 @ [Wcls|Wbox] + bias      2000x1024 @ 1024x405 (pad 512)
// fp32 emulated as bf16 split: A@B = Ah@Bh + Ah@Bl + Al@Bh.
// R4: single K-sweep — all 4 tiles (Ah,Al,Bh,Bl) resident per K-chunk,
// 3 MMA combos per residency (33% less global traffic + ldsm, 3x fewer syncs).
// ---------------------------------------------------------------------------

#define NUM_CLASSES 81
#define SCORE_THRESH 0.05f
#define BBOX_XFORM_CLIP 4.135166556742356f

#define RMAX 2000
#define KDIM 12544
#define HDIM 1024
#define NHEAD 512   // 405 used, padded

// --------------------------- device scratch -------------------------------
__device__ __nv_bfloat16 g_xh[RMAX * KDIM];
__device__ __nv_bfloat16 g_xl[RMAX * KDIM];
__device__ __nv_bfloat16 g_w6h[HDIM * KDIM];    // [N][K]
__device__ __nv_bfloat16 g_w6l[HDIM * KDIM];
__device__ __nv_bfloat16 g_w7h[HDIM * HDIM];
__device__ __nv_bfloat16 g_w7l[HDIM * HDIM];
__device__ __nv_bfloat16 g_whh[NHEAD * HDIM];   // rows 405..511 stay zero (.bss)
__device__ __nv_bfloat16 g_whl[NHEAD * HDIM];
__device__ float         g_bhead[NHEAD];
__device__ __nv_bfloat16 g_f6h[RMAX * HDIM];
__device__ __nv_bfloat16 g_f6l[RMAX * HDIM];
__device__ __nv_bfloat16 g_f7h[RMAX * HDIM];
__device__ __nv_bfloat16 g_f7l[RMAX * HDIM];
__device__ float         g_logits[RMAX * NHEAD];

// --------------------------- PTX helpers ----------------------------------
__device__ __forceinline__ uint32_t smem_to_u32(const void* p) {
    uint32_t a;
    asm("{ .reg .u64 t; cvta.to.shared.u64 t, %1; cvt.u32.u64 %0, t; }"
        : "=r"(a) : "l"(p));
    return a;
}
__device__ __forceinline__ void cp_async16(uint32_t dst, const void* src, bool pred) {
    int sz = pred ? 16 : 0;
    asm volatile("cp.async.cg.shared.global [%0], [%1], 16, %2;"
                 :: "r"(dst), "l"(src), "r"(sz) : "memory");
}
#define CP_COMMIT() asm volatile("cp.async.commit_group;" ::: "memory")
#define CP_WAIT(N)  asm volatile("cp.async.wait_group %0;" :: "n"(N) : "memory")

__device__ __forceinline__ void ldsm_x4(uint32_t& r0, uint32_t& r1,
                                        uint32_t& r2, uint32_t& r3, uint32_t addr) {
    asm volatile("ldmatrix.sync.aligned.m8n8.x4.shared.b16 {%0,%1,%2,%3}, [%4];"
                 : "=r"(r0), "=r"(r1), "=r"(r2), "=r"(r3) : "r"(addr));
}
__device__ __forceinline__ void mma16816(float* c, const uint32_t* a,
                                         uint32_t b0, uint32_t b1) {
    asm volatile(
        "mma.sync.aligned.m16n8k16.row.col.f32.bf16.bf16.f32 "
        "{%0,%1,%2,%3}, {%4,%5,%6,%7}, {%8,%9}, {%0,%1,%2,%3};"
        : "+f"(c[0]), "+f"(c[1]), "+f"(c[2]), "+f"(c[3])
        : "r"(a[0]), "r"(a[1]), "r"(a[2]), "r"(a[3]), "r"(b0), "r"(b1));
}

// swizzled smem offset for (row, 16B-chunk), 64B logical rows.
__device__ __forceinline__ uint32_t swoff(int row, int chunk) {
    return (uint32_t)(row * 64 + ((chunk ^ ((row >> 1) & 3)) << 4));
}

// --------------------------- conversion kernels ---------------------------
__global__ void split_f32_kernel(const float* __restrict__ X, size_t n4,
                                 __nv_bfloat16* __restrict__ Xh,
                                 __nv_bfloat16* __restrict__ Xl) {
    size_t i = (size_t)blockIdx.x * blockDim.x + threadIdx.x;
    size_t stride = (size_t)gridDim.x * blockDim.x;
    const float4* X4 = reinterpret_cast<const float4*>(X);
    __nv_bfloat162* H2 = reinterpret_cast<__nv_bfloat162*>(Xh);
    __nv_bfloat162* L2 = reinterpret_cast<__nv_bfloat162*>(Xl);
    for (; i < n4; i += stride) {
        float4 v = X4[i];
        __nv_bfloat16 hx = __float2bfloat16(v.x), hy = __float2bfloat16(v.y);
        __nv_bfloat16 hz = __float2bfloat16(v.z), hw = __float2bfloat16(v.w);
        __nv_bfloat16 lx = __float2bfloat16(v.x - __bfloat162float(hx));
        __nv_bfloat16 ly = __float2bfloat16(v.y - __bfloat162float(hy));
        __nv_bfloat16 lz = __float2bfloat16(v.z - __bfloat162float(hz));
        __nv_bfloat16 lw = __float2bfloat16(v.w - __bfloat162float(hw));
        H2[i * 2 + 0] = __nv_bfloat162(hx, hy);
        H2[i * 2 + 1] = __nv_bfloat162(hz, hw);
        L2[i * 2 + 0] = __nv_bfloat162(lx, ly);
        L2[i * 2 + 1] = __nv_bfloat162(lz, lw);
    }
}

// W[K][Nsrc] f32 -> Th/Tl[rowoff + n][K] bf16 (transpose + split), n guarded.
__global__ void transpose_split_kernel(const float* __restrict__ W, int K, int Nsrc,
                                       int ldT, int rowoff,
                                       __nv_bfloat16* __restrict__ Th,
                                       __nv_bfloat16* __restrict__ Tl) {
    __shared__ float t[32][33];
    const int n0 = blockIdx.x * 32;
    const int k0 = blockIdx.y * 32;
    const int tx = threadIdx.x, ty = threadIdx.y;  // 32 x 8
#pragma unroll
    for (int i = 0; i < 32; i += 8) {
        float v = 0.f;
        if (n0 + tx < Nsrc)
            v = W[(size_t)(k0 + ty + i) * Nsrc + n0 + tx];
        t[ty + i][tx] = v;
    }
    __syncthreads();
#pragma unroll
    for (int i = 0; i < 32; i += 8) {
        const int n = n0 + ty + i;
        if (n >= Nsrc) continue;
        float v = t[tx][ty + i];
        __nv_bfloat16 h = __float2bfloat16(v);
        __nv_bfloat16 l = __float2bfloat16(v - __bfloat162float(h));
        const size_t o = (size_t)(rowoff + n) * ldT + k0 + tx;
        Th[o] = h;
        Tl[o] = l;
    }
}

__global__ void bias_head_kernel(const float* __restrict__ bcls,
                                 const float* __restrict__ bbox_b,
                                 float* __restrict__ bh) {
    int t = threadIdx.x;  // 512
    float v = 0.f;
    if (t < NUM_CLASSES) v = bcls[t];
    else if (t < NUM_CLASSES + NUM_CLASSES * 4) v = bbox_b[t - NUM_CLASSES];
    bh[t] = v;
}

// --------------------------- HMMA split GEMM ------------------------------
// Single K-sweep: per 32-K chunk, stage holds Ah|Al|Bh|Bl (4 x 8KB = 32KB).
// 3 MMA combos per chunk accumulate into regs. 3-stage cp.async pipeline
// (96KB dynamic smem). Block 128x128, 8 warps of 32x64. K%32==0, N%128==0.
__global__ __launch_bounds__(256)
void hmma_gemm_split(int M, int N, int K,
                     const __nv_bfloat16* __restrict__ Ah,
                     const __nv_bfloat16* __restrict__ Al,
                     const __nv_bfloat16* __restrict__ Bh,
                     const __nv_bfloat16* __restrict__ Bl,
                     const float* __restrict__ bias, int do_relu,
                     float* __restrict__ C, int ldc,
                     __nv_bfloat16* __restrict__ Oh,
                     __nv_bfloat16* __restrict__ Ol, int ldo) {
    extern __shared__ char smem[];
    const uint32_t sbase = smem_to_u32(smem);
    const int tid = threadIdx.x, lane = tid & 31, wid = tid >> 5;
    const int bm = blockIdx.y * 128, bn = blockIdx.x * 128;
    const int wm = (wid & 3) * 32, wn = (wid >> 2) * 64;

    constexpr uint32_t STAGE = 32768u;  // Ah 8K | Al 8K | Bh 8K | Bl 8K

    // ---- cp.async per-thread addressing (step-invariant) ----
    uint32_t offA[2], offB[2];
    size_t gofA[2], gofB[2];
    bool predA[2];
#pragma unroll
    for (int i = 0; i < 2; ++i) {
        const int idx = tid + i * 256;           // 0..511
        const int row = idx >> 2, ch = idx & 3;  // 128 rows x 4 chunks(16B)
        offA[i] = swoff(row, ch);
        offB[i] = swoff(row, ch);
        const int ra = (bm + row < M) ? (bm + row) : (M - 1);
        predA[i] = (bm + row < M);
        gofA[i] = (size_t)ra * K + ch * 8;
        gofB[i] = (size_t)(bn + row) * K + ch * 8;
    }

    // ---- ldmatrix fragment offsets (within a tile) ----
    uint32_t aFrag[2][2];
#pragma unroll
    for (int mt = 0; mt < 2; ++mt) {
        const int row = wm + mt * 16 + (lane & 15);
#pragma unroll
        for (int kc = 0; kc < 2; ++kc)
            aFrag[mt][kc] = swoff(row, (lane >> 4) + kc * 2);
    }
    uint32_t bFrag[4][2];
#pragma unroll
    for (int nt = 0; nt < 4; ++nt) {
        const int row = wn + nt * 16 + ((lane & 7) | ((lane >> 4) << 3));
#pragma unroll
        for (int kc = 0; kc < 2; ++kc)
            bFrag[nt][kc] = swoff(row, ((lane >> 3) & 1) + kc * 2);
    }

    float acc[2][8][4];
#pragma unroll
    for (int mt = 0; mt < 2; ++mt)
#pragma unroll
        for (int nf = 0; nf < 8; ++nf)
#pragma unroll
            for (int k = 0; k < 4; ++k) acc[mt][nf][k] = 0.f;

    const int S = K / 32;

    auto issue = [&](int step) {
        const size_t k0 = (size_t)step * 32;
        const uint32_t st = (uint32_t)(step % 3) * STAGE;
#pragma unroll
        for (int i = 0; i < 2; ++i) {
            cp_async16(sbase + st + offA[i],          Ah + gofA[i] + k0, predA[i]);
            cp_async16(sbase + st + 8192 + offA[i],   Al + gofA[i] + k0, predA[i]);
            cp_async16(sbase + st + 16384 + offB[i],  Bh + gofB[i] + k0, true);
            cp_async16(sbase + st + 24576 + offB[i],  Bl + gofB[i] + k0, true);
        }
        CP_COMMIT();
    };

    issue(0);
    if (S > 1) issue(1);

#pragma unroll 1
    for (int s = 0; s < S; ++s) {
        if (s + 1 < S) { CP_WAIT(1); } else { CP_WAIT(0); }
        __syncthreads();
        if (s + 2 < S) issue(s + 2);

        const uint32_t base   = sbase + (uint32_t)(s % 3) * STAGE;
        const uint32_t baseAl = base + 8192u;
        const uint32_t baseBh = base + 16384u;
        const uint32_t baseBl = base + 24576u;
#pragma unroll
        for (int kc = 0; kc < 2; ++kc) {
            uint32_t aH[2][4], aL[2][4];
            ldsm_x4(aH[0][0], aH[0][1], aH[0][2], aH[0][3], base   + aFrag[0][kc]);
            ldsm_x4(aH[1][0], aH[1][1], aH[1][2], aH[1][3], base   + aFrag[1][kc]);
            ldsm_x4(aL[0][0], aL[0][1], aL[0][2], aL[0][3], baseAl + aFrag[0][kc]);
            ldsm_x4(aL[1][0], aL[1][1], aL[1][2], aL[1][3], baseAl + aFrag[1][kc]);
#pragma unroll
            for (int nt = 0; nt < 4; ++nt) {
                uint32_t bh0, bh1, bh2, bh3, bl0, bl1, bl2, bl3;
                ldsm_x4(bh0, bh1, bh2, bh3, baseBh + bFrag[nt][kc]);
                ldsm_x4(bl0, bl1, bl2, bl3, baseBl + bFrag[nt][kc]);
                // Ah @ Bh
                mma16816(acc[0][nt * 2 + 0], aH[0], bh0, bh1);
                mma16816(acc[0][nt * 2 + 1], aH[0], bh2, bh3);
                mma16816(acc[1][nt * 2 + 0], aH[1], bh0, bh1);
                mma16816(acc[1][nt * 2 + 1], aH[1], bh2, bh3);
                // Ah @ Bl
                mma16816(acc[0][nt * 2 + 0], aH[0], bl0, bl1);
                mma16816(acc[0][nt * 2 + 1], aH[0], bl2, bl3);
                mma16816(acc[1][nt * 2 + 0], aH[1], bl0, bl1);
                mma16816(acc[1][nt * 2 + 1], aH[1], bl2, bl3);
                // Al @ Bh
                mma16816(acc[0][nt * 2 + 0], aL[0], bh0, bh1);
                mma16816(acc[0][nt * 2 + 1], aL[0], bh2, bh3);
                mma16816(acc[1][nt * 2 + 0], aL[1], bh0, bh1);
                mma16816(acc[1][nt * 2 + 1], aL[1], bh2, bh3);
            }
        }
    }

    // ---- epilogue: bias (+relu), write C f32 and/or split bf16 ----
#pragma unroll
    for (int mt = 0; mt < 2; ++mt) {
#pragma unroll
        for (int nf = 0; nf < 8; ++nf) {
            const int col = bn + wn + nf * 8 + (lane & 3) * 2;
            const float b0 = bias[col], b1 = bias[col + 1];
#pragma unroll
            for (int half = 0; half < 2; ++half) {
                const int row = bm + wm + mt * 16 + (lane >> 2) + half * 8;
                if (row >= M) continue;
                float v0 = acc[mt][nf][half * 2 + 0] + b0;
                float v1 = acc[mt][nf][half * 2 + 1] + b1;
                if (do_relu) { v0 = fmaxf(v0, 0.f); v1 = fmaxf(v1, 0.f); }
                if (C)
                    *reinterpret_cast<float2*>(&C[(size_t)row * ldc + col]) =
                        make_float2(v0, v1);
                if (Oh) {
                    __nv_bfloat16 h0 = __float2bfloat16(v0);
                    __nv_bfloat16 h1 = __float2bfloat16(v1);
                    __nv_bfloat16 l0 = __float2bfloat16(v0 - __bfloat162float(h0));
                    __nv_bfloat16 l1 = __float2bfloat16(v1 - __bfloat162float(h1));
                    *reinterpret_cast<__nv_bfloat162*>(&Oh[(size_t)row * ldo + col]) =
                        __nv_bfloat162(h0, h1);
                    *reinterpret_cast<__nv_bfloat162*>(&Ol[(size_t)row * ldo + col]) =
                        __nv_bfloat162(l0, l1);
                }
            }
        }
    }
}

// --------------------------- postprocess ----------------------------------
__global__ __launch_bounds__(128)
void postprocess_kernel(const float* __restrict__ logits, int ldl,
                        const float* __restrict__ boxes,
                        float* __restrict__ out, int ldo) {
    const int r = blockIdx.x;
    const int t = threadIdx.x;
    __shared__ float sl[NUM_CLASSES * 5];  // 405
    __shared__ float smax, ssum;

    for (int i = t; i < NUM_CLASSES * 5; i += 128)
        sl[i] = logits[(size_t)r * ldl + i];
    __syncthreads();

    if (t == 0) {
        float m = -1e30f;
        for (int i = 0; i < NUM_CLASSES; ++i) m = fmaxf(m, sl[i]);
        float s = 0.f;
        for (int i = 0; i < NUM_CLASSES; ++i) s += expf(sl[i] - m);
        smax = m;
        ssum = s;
    }
    __syncthreads();

    if (t < NUM_CLASSES - 1) {
        const int j = t + 1;
        const float p = expf(sl[j] - smax) / ssum;
        const bool keep = p > SCORE_THRESH;

        const float bx0 = boxes[r * 4 + 0];
        const float by0 = boxes[r * 4 + 1];
        const float bx1 = boxes[r * 4 + 2];
        const float by1 = boxes[r * 4 + 3];
        const float w = bx1 - bx0 + 1.0f;
        const float hh = by1 - by0 + 1.0f;
        const float cx = bx0 + 0.5f * w;
        const float cy = by0 + 0.5f * hh;

        const float* reg = &sl[NUM_CLASSES + j * 4];
        const float dx = reg[0] * 0.1f;
        const float dy = reg[1] * 0.1f;
        const float dw = fminf(reg[2] * 0.2f, BBOX_XFORM_CLIP);
        const float dh = fminf(reg[3] * 0.2f, BBOX_XFORM_CLIP);

        const float pcx = dx * w + cx;
        const float pcy = dy * hh + cy;
        const float pw = expf(dw) * w;
        const float ph = expf(dh) * hh;

        float* orow = out + (size_t)r * ldo;
        orow[t] = keep ? p : 0.f;
        const int bo = (NUM_CLASSES - 1) + t * 4;
        orow[bo + 0] = keep ? (pcx - 0.5f * pw) : 0.f;
        orow[bo + 1] = keep ? (pcy - 0.5f * ph) : 0.f;
        orow[bo + 2] = keep ? (pcx + 0.5f * pw - 1.0f) : 0.f;
        orow[bo + 3] = keep ? (pcy + 0.5f * ph - 1.0f) : 0.f;
    }
}

// --------------------------- launch ---------------------------------------
extern "C" void kernel_launch(void* const* d_in, const int* in_sizes, int n_in,
                              void* d_out, int out_size) {
    const float* x      = (const float*)d_in[0];
    const float* boxes  = (const float*)d_in[1];
    const float* W6     = (const float*)d_in[2];
    const float* b6     = (const float*)d_in[3];
    const float* W7     = (const float*)d_in[4];
    const float* b7     = (const float*)d_in[5];
    const float* Wcls   = (const float*)d_in[6];
    const float* bcls   = (const float*)d_in[7];
    const float* Wbox   = (const float*)d_in[8];
    const float* bbox_b = (const float*)d_in[9];
    float* out = (float*)d_out;
    (void)n_in; (void)out_size;

    const int M  = in_sizes[1] / 4;       // 2000
    const int K1 = in_sizes[0] / M;       // 12544
    const int H  = in_sizes[3];           // 1024
    const int NC = in_sizes[7];           // 81
    const int OUTW = (NC - 1) * 5 + H;    // 1424

    __nv_bfloat16 *xh, *xl, *w6h, *w6l, *w7h, *w7l, *whh, *whl;
    __nv_bfloat16 *f6h, *f6l, *f7h, *f7l;
    float *bhead, *logits;
    cudaGetSymbolAddress((void**)&xh, g_xh);
    cudaGetSymbolAddress((void**)&xl, g_xl);
    cudaGetSymbolAddress((void**)&w6h, g_w6h);
    cudaGetSymbolAddress((void**)&w6l, g_w6l);
    cudaGetSymbolAddress((void**)&w7h, g_w7h);
    cudaGetSymbolAddress((void**)&w7l, g_w7l);
    cudaGetSymbolAddress((void**)&whh, g_whh);
    cudaGetSymbolAddress((void**)&whl, g_whl);
    cudaGetSymbolAddress((void**)&bhead, g_bhead);
    cudaGetSymbolAddress((void**)&f6h, g_f6h);
    cudaGetSymbolAddress((void**)&f6l, g_f6l);
    cudaGetSymbolAddress((void**)&f7h, g_f7h);
    cudaGetSymbolAddress((void**)&f7l, g_f7l);
    cudaGetSymbolAddress((void**)&logits, g_logits);

    const int SMEM_BYTES = 3 * 32768;  // 96KB
    cudaFuncSetAttribute(hmma_gemm_split,
                         cudaFuncAttributeMaxDynamicSharedMemorySize, SMEM_BYTES);

    // 1) split x
    split_f32_kernel<<<4096, 256>>>(x, ((size_t)M * K1) / 4, xh, xl);
    // 2) transpose+split weights
    transpose_split_kernel<<<dim3(H / 32, K1 / 32), dim3(32, 8)>>>(
        W6, K1, H, K1, 0, w6h, w6l);
    transpose_split_kernel<<<dim3(H / 32, H / 32), dim3(32, 8)>>>(
        W7, H, H, H, 0, w7h, w7l);
    transpose_split_kernel<<<dim3((NC + 31) / 32, H / 32), dim3(32, 8)>>>(
        Wcls, H, NC, H, 0, whh, whl);
    transpose_split_kernel<<<dim3((NC * 4 + 31) / 32, H / 32), dim3(32, 8)>>>(
        Wbox, H, NC * 4, H, NC, whh, whl);
    bias_head_kernel<<<1, NHEAD>>>(bcls, bbox_b, bhead);

    // 3) GEMM1: f6 -> out cols [400,1424) (f32) + split copy
    hmma_gemm_split<<<dim3(H / 128, (M + 127) / 128), 256, SMEM_BYTES>>>(
        M, H, K1, xh, xl, w6h, w6l, b6, 1,
        out + (NC - 1) * 5, OUTW, f6h, f6l, H);
    // 4) GEMM2: f7 split only
    hmma_gemm_split<<<dim3(H / 128, (M + 127) / 128), 256, SMEM_BYTES>>>(
        M, H, H, f6h, f6l, w7h, w7l, b7, 1,
        nullptr, 0, f7h, f7l, H);
    // 5) head GEMM: logits (no relu)
    hmma_gemm_split<<<dim3(NHEAD / 128, (M + 127) / 128), 256, SMEM_BYTES>>>(
        M, NHEAD, H, f7h, f7l, whh, whl, bhead, 0,
        logits, NHEAD, nullptr, nullptr, 0);
    // 6) postprocess
    postprocess_kernel<<<M, 128>>>(logits, NHEAD, boxes, out, OUTW);
}